// round 12
// baseline (speedup 1.0000x reference)
#include <cuda_runtime.h>
#include <cuda_fp16.h>
#include <math.h>

#define NB    64
#define NI    2048
#define KA    8
#define NO    32
#define OA    16
#define OUT   512

#define NSLOT_GEN  128
#define NSLOT_PASS 64

__device__ float g_S[NB * OUT];                      // cumulative sum of activations
__device__ float g_part[NSLOT_GEN * NB * OUT];       // partial preact, slot-partitioned (16 MB)
// votes fp16 as uint4 (8 halves = atoms 8c..8c+7 of capsule j=lane)
// index: ((b*NI + i)*2 + c)*32 + lane               -> 128 MB
__device__ uint4 g_votes[(size_t)NB * NI * 2 * 32];

typedef unsigned long long u64;

// ---- f32x2 helpers ----
__device__ __forceinline__ u64 fma2(u64 a, u64 b, u64 c) {
    u64 d; asm("fma.rn.f32x2 %0, %1, %2, %3;" : "=l"(d) : "l"(a), "l"(b), "l"(c)); return d;
}
__device__ __forceinline__ u64 pack2(float lo, float hi) {
    u64 d; asm("mov.b64 %0, {%1, %2};" : "=l"(d) : "f"(lo), "f"(hi)); return d;
}
__device__ __forceinline__ void unpack2(u64 v, float& lo, float& hi) {
    asm("mov.b64 {%0, %1}, %2;" : "=f"(lo), "=f"(hi) : "l"(v));
}
__device__ __forceinline__ void cp16(void* smem_dst, const void* gsrc) {
    unsigned s = (unsigned)__cvta_generic_to_shared(smem_dst);
    asm volatile("cp.async.cg.shared.global [%0], [%1], 16;" :: "r"(s), "l"(gsrc));
}
__device__ __forceinline__ int swz(int b) { return b ^ ((b >> 3) & 0x70); }

// ---------------------------------------------------------------- zero (S only)
__global__ void k_zero() {
    int t = blockIdx.x * blockDim.x + threadIdx.x;
    if (t < NB * OUT) g_S[t] = 0.0f;
}

// ---------------------------------------------------------------- gen + pass0
// grid = (NI/ITA = 128, NB/32 = 2), block 256 (8 warps). lane = j; warp owns 4 b.
// W[i] staged in smem (cp.async dbl buffer). Stores fp16 votes (uint4, coalesced)
// and writes pass-0 partial preact (route = 1/33) to slot blockIdx.x. No atomics.
#define ITA 16
__global__ void __launch_bounds__(256, 1)
k_gen(const float* __restrict__ x, const float* __restrict__ W) {
    __shared__ char ws[2 * KA * OUT * 4];     // 32 KB dbl-buffered W tile

    const int tid  = threadIdx.x;
    const int w    = tid >> 5;
    const int lane = tid & 31;
    const int it0  = blockIdx.x * ITA;
    const int b0   = blockIdx.y * 32 + w * 4;

    {   // prefetch first tile (16 KB = 1024 float4, 4 per thread)
        const float4* g = (const float4*)(W + (size_t)it0 * KA * OUT);
#pragma unroll
        for (int r = 0; r < 4; r++) { int f4 = tid + 256 * r; cp16(ws + swz(f4 * 16), &g[f4]); }
        asm volatile("cp.async.commit_group;" ::: "memory");
    }

    u64 acc[4][8];
#pragma unroll
    for (int bq = 0; bq < 4; bq++)
#pragma unroll
        for (int p = 0; p < 8; p++) acc[bq][p] = 0ull;
    const u64 c33 = pack2(1.0f / 33.0f, 1.0f / 33.0f);

    for (int ii = 0; ii < ITA; ii++) {
        asm volatile("cp.async.wait_group 0;" ::: "memory");
        __syncthreads();

        if (ii + 1 < ITA) {
            const float4* g = (const float4*)(W + (size_t)(it0 + ii + 1) * KA * OUT);
            char* dst = ws + ((ii + 1) & 1) * (KA * OUT * 4);
#pragma unroll
            for (int r = 0; r < 4; r++) { int f4 = tid + 256 * r; cp16(dst + swz(f4 * 16), &g[f4]); }
            asm volatile("cp.async.commit_group;" ::: "memory");
        }

        const char* Wc = ws + (ii & 1) * (KA * OUT * 4);
        const int i = it0 + ii;

        float xk[4][KA];
#pragma unroll
        for (int bq = 0; bq < 4; bq++) {
            const float4* xp = (const float4*)&x[((size_t)(b0 + bq) * NI + i) * KA];
            float4 x0 = __ldg(xp), x1 = __ldg(xp + 1);
            xk[bq][0]=x0.x; xk[bq][1]=x0.y; xk[bq][2]=x0.z; xk[bq][3]=x0.w;
            xk[bq][4]=x1.x; xk[bq][5]=x1.y; xk[bq][6]=x1.z; xk[bq][7]=x1.w;
        }

        u64 v[4][8];
#pragma unroll
        for (int bq = 0; bq < 4; bq++)
#pragma unroll
            for (int p = 0; p < 8; p++) v[bq][p] = 0ull;

#pragma unroll
        for (int k = 0; k < KA; k++) {
            u64 xb[4];
#pragma unroll
            for (int bq = 0; bq < 4; bq++) xb[bq] = pack2(xk[bq][k], xk[bq][k]);
#pragma unroll
            for (int q = 0; q < 4; q++) {
                ulonglong2 wv = *(const ulonglong2*)(Wc + swz(k * 2048 + lane * 64 + q * 16));
#pragma unroll
                for (int bq = 0; bq < 4; bq++) {
                    v[bq][2*q]   = fma2(xb[bq], wv.x, v[bq][2*q]);
                    v[bq][2*q+1] = fma2(xb[bq], wv.y, v[bq][2*q+1]);
                }
            }
        }

#pragma unroll
        for (int bq = 0; bq < 4; bq++) {
            unsigned h[8];
#pragma unroll
            for (int p = 0; p < 8; p++) {
                acc[bq][p] = fma2(c33, v[bq][p], acc[bq][p]);
                float f0, f1; unpack2(v[bq][p], f0, f1);
                __half2 hh = __floats2half2_rn(f0, f1);
                h[p] = *(unsigned*)&hh;
            }
            uint4* dst = &g_votes[(((size_t)(b0 + bq) * NI + i) * 2) * 32 + lane];
            dst[0]  = make_uint4(h[0], h[1], h[2], h[3]);
            dst[32] = make_uint4(h[4], h[5], h[6], h[7]);
        }
    }

    // slot-partitioned partial store (no atomics): slot = blockIdx.x in [0,128)
#pragma unroll
    for (int bq = 0; bq < 4; bq++) {
        float4* dst = (float4*)&g_part[((size_t)blockIdx.x * NB + (b0 + bq)) * OUT + lane * OA];
#pragma unroll
        for (int q = 0; q < 4; q++) {
            float a0, a1, a2, a3;
            unpack2(acc[bq][2*q],   a0, a1);
            unpack2(acc[bq][2*q+1], a2, a3);
            dst[q] = make_float4(a0, a1, a2, a3);
        }
    }
}

// ---------------------------------------------------------------- route pass
// grid = (8, 64): warp = (b = blockIdx.y, 32-i chunk), lane = j.  Plain unroll-4
// loop (proven), 2x LDG.128 per i. Partials -> slot blockIdx.x*8 + w. No atomics.
#define IW 32
__global__ void __launch_bounds__(256)
k_pass() {
    const int tid  = threadIdx.x;
    const int w    = tid >> 5;
    const int lane = tid & 31;
    const int b    = blockIdx.y;
    const int i0   = (blockIdx.x * 8 + w) * IW;

    // S[b, lane*16 .. +16) in 8 u64 regs
    u64 s[8];
    {
        const ulonglong2* sp = (const ulonglong2*)&g_S[(size_t)b * OUT + lane * OA];
#pragma unroll
        for (int q = 0; q < 4; q++) { ulonglong2 t = __ldg(sp + q); s[2*q] = t.x; s[2*q+1] = t.y; }
    }

    u64 acc[8];
#pragma unroll
    for (int p = 0; p < 8; p++) acc[p] = 0ull;

    const uint4* src = &g_votes[(((size_t)b * NI + i0) * 2) * 32 + lane];

#pragma unroll 4
    for (int m = 0; m < IW; m++) {
        uint4 u0 = __ldg(src + (size_t)m * 64);
        uint4 u1 = __ldg(src + (size_t)m * 64 + 32);

        u64 v[8];
        {
            float2 f;
            f = __half22float2(*(__half2*)&u0.x); v[0] = pack2(f.x, f.y);
            f = __half22float2(*(__half2*)&u0.y); v[1] = pack2(f.x, f.y);
            f = __half22float2(*(__half2*)&u0.z); v[2] = pack2(f.x, f.y);
            f = __half22float2(*(__half2*)&u0.w); v[3] = pack2(f.x, f.y);
            f = __half22float2(*(__half2*)&u1.x); v[4] = pack2(f.x, f.y);
            f = __half22float2(*(__half2*)&u1.y); v[5] = pack2(f.x, f.y);
            f = __half22float2(*(__half2*)&u1.z); v[6] = pack2(f.x, f.y);
            f = __half22float2(*(__half2*)&u1.w); v[7] = pack2(f.x, f.y);
        }

        u64 l2 = 0ull;
#pragma unroll
        for (int p = 0; p < 8; p++) l2 = fma2(v[p], s[p], l2);
        float a0, a1; unpack2(l2, a0, a1);
        float e = __expf(a0 + a1);

        float tot = e;
#pragma unroll
        for (int d = 16; d > 0; d >>= 1)
            tot += __shfl_xor_sync(0xFFFFFFFFu, tot, d);
        float r = __fdividef(e, 1.0f + tot);       // leaky softmax (leak logit 0)

        u64 r2 = pack2(r, r);
#pragma unroll
        for (int p = 0; p < 8; p++) acc[p] = fma2(r2, v[p], acc[p]);
    }

    // slot-partitioned partial store: slot = blockIdx.x*8 + w  (covers 0..63 per b)
    const int slot = blockIdx.x * 8 + w;
    float4* dst = (float4*)&g_part[((size_t)slot * NB + b) * OUT + lane * OA];
#pragma unroll
    for (int q = 0; q < 4; q++) {
        float a0, a1, a2, a3;
        unpack2(acc[2*q],   a0, a1);
        unpack2(acc[2*q+1], a2, a3);
        dst[q] = make_float4(a0, a1, a2, a3);
    }
}

// ---------------------------------------------------------------- squash
// grid = 64 (b), block = 512. Sums NS partial slots + bias, squashes,
// writes out and updates S.
template<int NS>
__global__ void k_squash(const float* __restrict__ bias, float* __restrict__ out) {
    const int b = blockIdx.x;
    const int t = threadIdx.x;

    float p = bias[t];
    const float* base = &g_part[(size_t)b * OUT + t];
#pragma unroll 16
    for (int s = 0; s < NS; s++)
        p += __ldg(base + (size_t)s * NB * OUT);

    float sq = p * p;
#pragma unroll
    for (int d = 1; d < OA; d <<= 1)
        sq += __shfl_xor_sync(0xFFFFFFFFu, sq, d);
    float nrm = sqrtf(sq);
    float scale = nrm / (1.0f + sq);
    float a = p * scale;

    out[b * OUT + t] = a;
    g_S[b * OUT + t] += a;
}

// ---------------------------------------------------------------- launch
extern "C" void kernel_launch(void* const* d_in, const int* in_sizes, int n_in,
                              void* d_out, int out_size) {
    const float* x    = (const float*)d_in[0];   // [64, 2048, 8]
    const float* W    = (const float*)d_in[1];   // [2048, 8, 512]
    const float* bias = (const float*)d_in[2];   // [32, 16]
    float* out = (float*)d_out;                  // [64, 32, 16]

    k_zero<<<64, 512>>>();
    k_gen<<<dim3(NI / ITA, NB / 32), 256>>>(x, W);   // votes + pass 0 partials (128 slots)
    k_squash<NSLOT_GEN><<<NB, 512>>>(bias, out);
    k_pass<<<dim3(8, NB), 256>>>();                  // pass 1 partials (64 slots)
    k_squash<NSLOT_PASS><<<NB, 512>>>(bias, out);
    k_pass<<<dim3(8, NB), 256>>>();                  // pass 2 partials
    k_squash<NSLOT_PASS><<<NB, 512>>>(bias, out);
}

// round 14
// speedup vs baseline: 1.2713x; 1.2713x over previous
#include <cuda_runtime.h>
#include <cuda_fp16.h>
#include <math.h>

#define NB    64
#define NI    2048
#define KA    8
#define NO    32
#define OA    16
#define OUT   512

#define NSLOT 64

__device__ float g_S[NB * OUT];                 // cumulative sum of activations
__device__ float g_part[NSLOT * NB * OUT];      // partial preact, slot-partitioned (8 MB)
// votes fp16, SoA-chunked: uint2 (4 halves = atoms 4c..4c+3 of capsule j=lane)
// index: ((b*NI + i)*4 + c)*32 + lane          -> 128 MB
__device__ uint2 g_votes[(size_t)NB * NI * 4 * 32];

typedef unsigned long long u64;

// ---- f32x2 helpers ----
__device__ __forceinline__ u64 fma2(u64 a, u64 b, u64 c) {
    u64 d; asm("fma.rn.f32x2 %0, %1, %2, %3;" : "=l"(d) : "l"(a), "l"(b), "l"(c)); return d;
}
__device__ __forceinline__ u64 pack2(float lo, float hi) {
    u64 d; asm("mov.b64 %0, {%1, %2};" : "=l"(d) : "f"(lo), "f"(hi)); return d;
}
__device__ __forceinline__ void unpack2(u64 v, float& lo, float& hi) {
    asm("mov.b64 {%0, %1}, %2;" : "=f"(lo), "=f"(hi) : "l"(v));
}
__device__ __forceinline__ void cp16(void* smem_dst, const void* gsrc) {
    unsigned s = (unsigned)__cvta_generic_to_shared(smem_dst);
    asm volatile("cp.async.cg.shared.global [%0], [%1], 16;" :: "r"(s), "l"(gsrc));
}
__device__ __forceinline__ int swz(int b) { return b ^ ((b >> 3) & 0x70); }

// ---------------------------------------------------------------- zero (S only)
__global__ void k_zero() {
    int t = blockIdx.x * blockDim.x + threadIdx.x;
    if (t < NB * OUT) g_S[t] = 0.0f;
}

// ---------------------------------------------------------------- gen + pass0
// grid = (NI/32 = 64, NB/32 = 2), block 256 (8 warps). lane = j; warp owns 4 b.
// W[i] staged in smem (cp.async dbl buffer). Stores fp16 votes (uint2, coalesced)
// and writes pass-0 partial preact (route = 1/33) to slot blockIdx.x. No atomics.
#define ITA 32
__global__ void __launch_bounds__(256, 1)
k_gen(const float* __restrict__ x, const float* __restrict__ W) {
    __shared__ char ws[2 * KA * OUT * 4];     // 32 KB dbl-buffered W tile

    const int tid  = threadIdx.x;
    const int w    = tid >> 5;
    const int lane = tid & 31;
    const int it0  = blockIdx.x * ITA;
    const int b0   = blockIdx.y * 32 + w * 4;

    {   // prefetch first tile (16 KB = 1024 float4, 4 per thread)
        const float4* g = (const float4*)(W + (size_t)it0 * KA * OUT);
#pragma unroll
        for (int r = 0; r < 4; r++) { int f4 = tid + 256 * r; cp16(ws + swz(f4 * 16), &g[f4]); }
        asm volatile("cp.async.commit_group;" ::: "memory");
    }

    u64 acc[4][8];
#pragma unroll
    for (int bq = 0; bq < 4; bq++)
#pragma unroll
        for (int p = 0; p < 8; p++) acc[bq][p] = 0ull;
    const u64 c33 = pack2(1.0f / 33.0f, 1.0f / 33.0f);

    for (int ii = 0; ii < ITA; ii++) {
        asm volatile("cp.async.wait_group 0;" ::: "memory");
        __syncthreads();

        if (ii + 1 < ITA) {
            const float4* g = (const float4*)(W + (size_t)(it0 + ii + 1) * KA * OUT);
            char* dst = ws + ((ii + 1) & 1) * (KA * OUT * 4);
#pragma unroll
            for (int r = 0; r < 4; r++) { int f4 = tid + 256 * r; cp16(dst + swz(f4 * 16), &g[f4]); }
            asm volatile("cp.async.commit_group;" ::: "memory");
        }

        const char* Wc = ws + (ii & 1) * (KA * OUT * 4);
        const int i = it0 + ii;

        float xk[4][KA];
#pragma unroll
        for (int bq = 0; bq < 4; bq++) {
            const float4* xp = (const float4*)&x[((size_t)(b0 + bq) * NI + i) * KA];
            float4 x0 = __ldg(xp), x1 = __ldg(xp + 1);
            xk[bq][0]=x0.x; xk[bq][1]=x0.y; xk[bq][2]=x0.z; xk[bq][3]=x0.w;
            xk[bq][4]=x1.x; xk[bq][5]=x1.y; xk[bq][6]=x1.z; xk[bq][7]=x1.w;
        }

        u64 v[4][8];
#pragma unroll
        for (int bq = 0; bq < 4; bq++)
#pragma unroll
            for (int p = 0; p < 8; p++) v[bq][p] = 0ull;

#pragma unroll
        for (int k = 0; k < KA; k++) {
            u64 xb[4];
#pragma unroll
            for (int bq = 0; bq < 4; bq++) xb[bq] = pack2(xk[bq][k], xk[bq][k]);
#pragma unroll
            for (int q = 0; q < 4; q++) {
                ulonglong2 wv = *(const ulonglong2*)(Wc + swz(k * 2048 + lane * 64 + q * 16));
#pragma unroll
                for (int bq = 0; bq < 4; bq++) {
                    v[bq][2*q]   = fma2(xb[bq], wv.x, v[bq][2*q]);
                    v[bq][2*q+1] = fma2(xb[bq], wv.y, v[bq][2*q+1]);
                }
            }
        }

#pragma unroll
        for (int bq = 0; bq < 4; bq++) {
            unsigned h[8];
#pragma unroll
            for (int p = 0; p < 8; p++) {
                acc[bq][p] = fma2(c33, v[bq][p], acc[bq][p]);
                float f0, f1; unpack2(v[bq][p], f0, f1);
                __half2 hh = __floats2half2_rn(f0, f1);
                h[p] = *(unsigned*)&hh;
            }
            uint2* dst = &g_votes[(((size_t)(b0 + bq) * NI + i) * 4) * 32 + lane];
#pragma unroll
            for (int c = 0; c < 4; c++)
                dst[c * 32] = make_uint2(h[2*c], h[2*c+1]);
        }
    }

    // slot-partitioned partial store (no atomics): slot = blockIdx.x
#pragma unroll
    for (int bq = 0; bq < 4; bq++) {
        float4* dst = (float4*)&g_part[((size_t)blockIdx.x * NB + (b0 + bq)) * OUT + lane * OA];
#pragma unroll
        for (int q = 0; q < 4; q++) {
            float a0, a1, a2, a3;
            unpack2(acc[bq][2*q],   a0, a1);
            unpack2(acc[bq][2*q+1], a2, a3);
            dst[q] = make_float4(a0, a1, a2, a3);
        }
    }
}

// ---------------------------------------------------------------- route pass
// grid = (8, 64): warp = (b = blockIdx.y, 32-i chunk), lane = j.  R10 inner loop
// with unroll 8 (≈32 LDG.64 front-batched per warp). Partials -> slot
// blockIdx.x*8 + w. No atomics.
#define IW 32
__global__ void __launch_bounds__(256)
k_pass() {
    const int tid  = threadIdx.x;
    const int w    = tid >> 5;
    const int lane = tid & 31;
    const int b    = blockIdx.y;
    const int i0   = (blockIdx.x * 8 + w) * IW;

    // S[b, lane*16 .. +16) in 8 u64 regs
    u64 s[8];
    {
        const ulonglong2* sp = (const ulonglong2*)&g_S[(size_t)b * OUT + lane * OA];
#pragma unroll
        for (int q = 0; q < 4; q++) { ulonglong2 t = __ldg(sp + q); s[2*q] = t.x; s[2*q+1] = t.y; }
    }

    u64 acc[8];
#pragma unroll
    for (int p = 0; p < 8; p++) acc[p] = 0ull;

    const uint2* src = &g_votes[(((size_t)b * NI + i0) * 4) * 32 + lane];

#pragma unroll 8
    for (int m = 0; m < IW; m++) {
        uint2 u[4];
#pragma unroll
        for (int c = 0; c < 4; c++) u[c] = __ldg(src + (size_t)m * 128 + c * 32);

        u64 v[8];
#pragma unroll
        for (int c = 0; c < 4; c++) {
            float2 f0 = __half22float2(*(__half2*)&u[c].x);
            float2 f1 = __half22float2(*(__half2*)&u[c].y);
            v[2*c]   = pack2(f0.x, f0.y);
            v[2*c+1] = pack2(f1.x, f1.y);
        }

        u64 l2 = 0ull;
#pragma unroll
        for (int p = 0; p < 8; p++) l2 = fma2(v[p], s[p], l2);
        float a0, a1; unpack2(l2, a0, a1);
        float e = __expf(a0 + a1);

        float tot = e;
#pragma unroll
        for (int d = 16; d > 0; d >>= 1)
            tot += __shfl_xor_sync(0xFFFFFFFFu, tot, d);
        float r = __fdividef(e, 1.0f + tot);       // leaky softmax (leak logit 0)

        u64 r2 = pack2(r, r);
#pragma unroll
        for (int p = 0; p < 8; p++) acc[p] = fma2(r2, v[p], acc[p]);
    }

    // slot-partitioned partial store: slot = blockIdx.x*8 + w  (covers 0..63 per b)
    const int slot = blockIdx.x * 8 + w;
    float4* dst = (float4*)&g_part[((size_t)slot * NB + b) * OUT + lane * OA];
#pragma unroll
    for (int q = 0; q < 4; q++) {
        float a0, a1, a2, a3;
        unpack2(acc[2*q],   a0, a1);
        unpack2(acc[2*q+1], a2, a3);
        dst[q] = make_float4(a0, a1, a2, a3);
    }
}

// ---------------------------------------------------------------- squash
// grid = 64 (b), block = 512. Sums the 64 partial slots + bias, squashes,
// writes out and updates S.
__global__ void k_squash(const float* __restrict__ bias, float* __restrict__ out) {
    const int b = blockIdx.x;
    const int t = threadIdx.x;

    float p = bias[t];
    const float* base = &g_part[(size_t)b * OUT + t];
#pragma unroll 16
    for (int s = 0; s < NSLOT; s++)
        p += __ldg(base + (size_t)s * NB * OUT);

    float sq = p * p;
#pragma unroll
    for (int d = 1; d < OA; d <<= 1)
        sq += __shfl_xor_sync(0xFFFFFFFFu, sq, d);
    float nrm = sqrtf(sq);
    float scale = nrm / (1.0f + sq);
    float a = p * scale;

    out[b * OUT + t] = a;
    g_S[b * OUT + t] += a;
}

// ---------------------------------------------------------------- launch
extern "C" void kernel_launch(void* const* d_in, const int* in_sizes, int n_in,
                              void* d_out, int out_size) {
    const float* x    = (const float*)d_in[0];   // [64, 2048, 8]
    const float* W    = (const float*)d_in[1];   // [2048, 8, 512]
    const float* bias = (const float*)d_in[2];   // [32, 16]
    float* out = (float*)d_out;                  // [64, 32, 16]

    k_zero<<<64, 512>>>();
    k_gen<<<dim3(NI / ITA, NB / 32), 256>>>(x, W);   // votes + pass 0 partials
    k_squash<<<NB, 512>>>(bias, out);
    k_pass<<<dim3(8, NB), 256>>>();                  // pass 1 partials
    k_squash<<<NB, 512>>>(bias, out);
    k_pass<<<dim3(8, NB), 256>>>();                  // pass 2 partials
    k_squash<<<NB, 512>>>(bias, out);
}